// round 16
// baseline (speedup 1.0000x reference)
#include <cuda_runtime.h>
#include <cuda_fp16.h>
#include <cstdint>
#include <math.h>

#define BB 32768
#define DD 128
#define HH 1024
#define OO 929
#define OPAD 1024

// ---------------- scratch (__device__ globals; allocation-free rule) -------
__device__ __half g_x[(size_t)BB * DD];
__device__ __half g_h1[(size_t)BB * HH];
__device__ __half g_h2[(size_t)BB * HH];
__device__ __half g_w1[(size_t)HH * DD];    // [N][K]
__device__ __half g_w2[(size_t)HH * HH];    // [N][K]
__device__ __half g_w3[(size_t)OPAD * HH];  // [Npad][K]
__device__ float g_logits[(size_t)BB * OPAD];

// ---------------- portable PTX helpers (valid on target sm_103) -----------
__device__ __forceinline__ uint32_t smem_u32(const void* p) {
    uint32_t a;
    asm("{ .reg .u64 t; cvta.to.shared.u64 t, %1; cvt.u32.u64 %0, t; }" : "=r"(a) : "l"(p));
    return a;
}
__device__ __forceinline__ void cp16(uint32_t dst, const void* src) {
    asm volatile("cp.async.cg.shared.global [%0], [%1], 16;" :: "r"(dst), "l"(src) : "memory");
}
__device__ __forceinline__ void cp_commit() {
    asm volatile("cp.async.commit_group;" ::: "memory");
}
template <int N>
__device__ __forceinline__ void cp_wait() {
    asm volatile("cp.async.wait_group %0;" :: "n"(N) : "memory");
}
__device__ __forceinline__ void ldsm_x4(uint32_t* r, uint32_t addr) {
    asm volatile("ldmatrix.sync.aligned.m8n8.x4.shared.b16 {%0,%1,%2,%3}, [%4];"
                 : "=r"(r[0]), "=r"(r[1]), "=r"(r[2]), "=r"(r[3]) : "r"(addr));
}
__device__ __forceinline__ void mma_f16(float* c, const uint32_t* a, uint32_t b0, uint32_t b1) {
    asm volatile(
        "mma.sync.aligned.m16n8k16.row.col.f32.f16.f16.f32 "
        "{%0,%1,%2,%3}, {%4,%5,%6,%7}, {%8,%9}, {%0,%1,%2,%3};"
        : "+f"(c[0]), "+f"(c[1]), "+f"(c[2]), "+f"(c[3])
        : "r"(a[0]), "r"(a[1]), "r"(a[2]), "r"(a[3]), "r"(b0), "r"(b1));
}

// ---------------- conversion kernels ---------------------------------------
__global__ void tohalf_kernel(const float* __restrict__ in, __half* __restrict__ out, size_t n) {
    size_t i = (size_t)blockIdx.x * 256 + threadIdx.x;
    if (i >= n) return;
    out[i] = __float2half(in[i]);
}

// Coalesced 32x32 tiled transpose: out[n*K + k] = half(W[k*N + n]), zero-pad n>=N.
// grid = (K/32, Npad/32), block = (32, 8). K and Npad are multiples of 32.
__global__ void transpose_half_tiled(const float* __restrict__ W,
                                     __half* __restrict__ outw,
                                     int K, int N) {
    __shared__ float t[32][33];
    const int k0 = blockIdx.x * 32, n0 = blockIdx.y * 32;
    const int tx = threadIdx.x, ty = threadIdx.y;
#pragma unroll
    for (int i = 0; i < 4; i++) {
        int k = k0 + ty + i * 8;
        int n = n0 + tx;
        t[ty + i * 8][tx] = (n < N) ? W[(size_t)k * N + n] : 0.f;
    }
    __syncthreads();
#pragma unroll
    for (int i = 0; i < 4; i++) {
        int n = n0 + ty + i * 8;
        int k = k0 + tx;
        outw[(size_t)n * K + k] = __float2half(t[tx][ty + i * 8]);
    }
}

// ---------------- mma.sync fp16 GEMM ----------------------------------------
// C(128x128) = act(A[M,K] @ B^T[N,K] + bias), A and B plain fp16.
// 256 threads = 8 warps, warp tile 32x64. BK=64 (128B rows, xor-8 swizzle),
// 3-stage cp.async pipeline, 96 KB smem -> 2 CTAs/SM.
#define BM 128
#define BN 128
#define BK 64
#define NSTAGE 3
// stage: 2 arrays of [128 rows][128B] = 16KB each
#define OFF_A   0
#define OFF_B   16384
#define STAGE_BYTES 32768

__device__ __forceinline__ void load_stage(uint32_t sbase,
    const __half* A, const __half* B, int K, int k0, int tid)
{
#pragma unroll
    for (int t = 0; t < 4; t++) {
        int id = tid + t * 256;            // 0..1023 over 128 rows x 8 chunks
        int r = id >> 3;
        int c = id & 7;
        int sc = c ^ (r & 7);              // xor swizzle, 16B granules, 8-wide
        uint32_t doff = (uint32_t)(r * 128 + sc * 16);
        size_t goff = (size_t)r * K + k0 + c * 8;
        cp16(sbase + OFF_A + doff, A + goff);
        cp16(sbase + OFF_B + doff, B + goff);
    }
}

// ACT: 0=none 1=elu 2=sigmoid.
// EPI: 0=write fp16 activations (stride HH), 1=write f32 (stride OPAD, guard col<Ncols)
template <int ACT, int EPI>
__global__ __launch_bounds__(256, 2)
void gemm_mma(const __half* __restrict__ A0, const __half* __restrict__ B0,
              const float* __restrict__ bias,
              __half* __restrict__ Ch, float* __restrict__ Cf, int K, int Ncols)
{
    extern __shared__ char smem[];
    const uint32_t sm0 = smem_u32(smem);
    const int tid = threadIdx.x;
    const int wid = tid >> 5;
    const int lane = tid & 31;
    const int wm = wid & 3;                // 4 m-slices of 32
    const int wn = wid >> 2;               // 2 n-slices of 64
    const int bm = blockIdx.y * BM;
    const int bn = blockIdx.x * BN;

    const __half* A = A0 + (size_t)bm * K;
    const __half* B = B0 + (size_t)bn * K;

    const int KT = K / BK;

    float acc[2][8][4];
#pragma unroll
    for (int i = 0; i < 2; i++)
#pragma unroll
        for (int j = 0; j < 8; j++)
#pragma unroll
            for (int q = 0; q < 4; q++) acc[i][j][q] = 0.f;

    // ldmatrix per-lane address components
    const int a_moff = lane & 15;
    const int a_kadd = lane >> 4;                       // 0/1
    const int b_noff = (lane & 7) | ((lane & 16) >> 1); // 0..15
    const int b_kadd = (lane >> 3) & 1;

    // prologue: fill NSTAGE-1 stages
#pragma unroll
    for (int s = 0; s < NSTAGE - 1; s++) {
        if (s < KT) load_stage(sm0 + s * STAGE_BYTES, A, B, K, s * BK, tid);
        cp_commit();
    }

    for (int kt = 0; kt < KT; kt++) {
        cp_wait<NSTAGE - 2>();
        __syncthreads();
        // Single barrier: it also proves every warp finished reading stage
        // (kt-1)%NSTAGE, which is the one the next load overwrites.

        int nk = kt + NSTAGE - 1;
        if (nk < KT)
            load_stage(sm0 + (nk % NSTAGE) * STAGE_BYTES, A, B, K, nk * BK, tid);
        cp_commit();

        const uint32_t sbase = sm0 + (kt % NSTAGE) * STAGE_BYTES;

#pragma unroll
        for (int s = 0; s < 4; s++) {                 // four k16 steps in BK=64
            uint32_t af[2][4];
            const int kca = 2 * s + a_kadd;           // 0..7 granules
#pragma unroll
            for (int i = 0; i < 2; i++) {
                int r = wm * 32 + i * 16 + a_moff;
                uint32_t off = (uint32_t)(r * 128 + ((kca ^ (r & 7)) * 16));
                ldsm_x4(af[i], sbase + OFF_A + off);
            }
            const int kcb = 2 * s + b_kadd;
#pragma unroll
            for (int jp = 0; jp < 4; jp++) {
                uint32_t bf[4];
                int rn = wn * 64 + jp * 16 + b_noff;
                uint32_t off = (uint32_t)(rn * 128 + ((kcb ^ (rn & 7)) * 16));
                ldsm_x4(bf, sbase + OFF_B + off);
#pragma unroll
                for (int i = 0; i < 2; i++) {
                    mma_f16(acc[i][2 * jp],     af[i], bf[0], bf[1]);
                    mma_f16(acc[i][2 * jp + 1], af[i], bf[2], bf[3]);
                }
            }
        }
    }

    // ---- epilogue ----
#pragma unroll
    for (int i = 0; i < 2; i++) {
#pragma unroll
        for (int j = 0; j < 8; j++) {
            const int row0 = bm + wm * 32 + i * 16 + (lane >> 2);
            const int col = bn + wn * 64 + j * 8 + (lane & 3) * 2;
            if (EPI == 0) {
                float bi0 = bias[col], bi1 = bias[col + 1];
#pragma unroll
                for (int h = 0; h < 2; h++) {       // h=0: rows l/4, h=1: +8
                    int row = row0 + h * 8;
                    float v0 = acc[i][j][2 * h] + bi0;
                    float v1 = acc[i][j][2 * h + 1] + bi1;
                    if (ACT == 1) {
                        v0 = (v0 > 0.f) ? v0 : expm1f(v0);
                        v1 = (v1 > 0.f) ? v1 : expm1f(v1);
                    } else if (ACT == 2) {
                        v0 = 1.f / (1.f + __expf(-v0));
                        v1 = 1.f / (1.f + __expf(-v1));
                    }
                    __half2 h2;
                    h2.x = __float2half(v0);
                    h2.y = __float2half(v1);
                    *(__half2*)(Ch + (size_t)row * HH + col) = h2;
                }
            } else {
#pragma unroll
                for (int h = 0; h < 2; h++) {
                    int row = row0 + h * 8;
                    if (col < Ncols)
                        Cf[(size_t)row * OPAD + col] = acc[i][j][2 * h] + bias[col];
                    if (col + 1 < Ncols)
                        Cf[(size_t)row * OPAD + col + 1] = acc[i][j][2 * h + 1] + bias[col + 1];
                }
            }
        }
    }
}

// ---------------- Gumbel-softmax (stride-1024 logits, no-max formulation) --
// Safe without max subtraction: y = (logit + g)/0.8 with g in [-3.8, ~16.5]
// and |logit| small -> y <= ~21, exp(y) <= 1.3e9, segment sums < 1e12 << FLT_MAX.
// All segments keep e values in registers (measured fastest vs smem/global
// scratch variants in R11/R12).
__device__ __forceinline__ float warp_sum(float v) {
#pragma unroll
    for (int d = 16; d; d >>= 1) v += __shfl_xor_sync(0xffffffffu, v, d);
    return v;
}

__device__ __forceinline__ float gumbel_e(float logit, float uu) {
    float g = -__logf(-__logf(uu + 1e-20f) + 1e-20f);
    return __expf((logit + g) * 1.25f);
}

template <int N>
__device__ __forceinline__ void seg_softmax(const float* __restrict__ lrow,
                                            const float* __restrict__ urow,
                                            float* __restrict__ orow,
                                            int off, int lane)
{
    constexpr int NI = (N + 31) / 32;
    float y[NI];
    float s = 0.f;
#pragma unroll
    for (int i = 0; i < NI; i++) {
        int idx = lane + i * 32;
        float e = 0.f;
        if (idx < N) e = gumbel_e(lrow[off + idx], urow[off + idx]);
        y[i] = e;
        s += e;
    }
    s = warp_sum(s);
    float inv = 1.f / s;
#pragma unroll
    for (int i = 0; i < NI; i++) {
        int idx = lane + i * 32;
        if (idx < N) orow[off + idx] = y[i] * inv;
    }
}

__global__ __launch_bounds__(256)
void gumbel_kernel(const float* __restrict__ logits,
                   const float* __restrict__ u,
                   float* __restrict__ out)
{
    int w = (blockIdx.x * 256 + threadIdx.x) >> 5;
    int lane = threadIdx.x & 31;
    if (w >= BB) return;
    const float* lrow = logits + (size_t)w * OPAD;
    const float* urow = u + (size_t)w * OO;
    float* orow = out + (size_t)w * OO;

    seg_softmax<29>(lrow, urow, orow, 0, lane);
    seg_softmax<2>(lrow, urow, orow, 29, lane);
    if (lane == 0) orow[31] = lrow[31];
    seg_softmax<6>(lrow, urow, orow, 32, lane);
    seg_softmax<7>(lrow, urow, orow, 38, lane);
    seg_softmax<59>(lrow, urow, orow, 45, lane);
    if (lane == 0) orow[104] = lrow[104];
    seg_softmax<24>(lrow, urow, orow, 105, lane);
    seg_softmax<76>(lrow, urow, orow, 129, lane);
    seg_softmax<711>(lrow, urow, orow, 205, lane);
    seg_softmax<3>(lrow, urow, orow, 916, lane);
    seg_softmax<9>(lrow, urow, orow, 919, lane);
    if (lane == 0) orow[928] = lrow[928];
}

// ---------------------------------------------------------------------------
extern "C" void kernel_launch(void* const* d_in, const int* in_sizes, int n_in,
                              void* d_out, int out_size)
{
    const float* x  = (const float*)d_in[0];
    const float* W1 = (const float*)d_in[1];
    const float* b1 = (const float*)d_in[2];
    const float* W2 = (const float*)d_in[3];
    const float* b2 = (const float*)d_in[4];
    const float* W3 = (const float*)d_in[5];
    const float* b3 = (const float*)d_in[6];
    const float* u  = (const float*)d_in[7];
    float* out = (float*)d_out;

    __half *xh, *h1, *h2, *w1, *w2, *w3;
    float* lg;
    cudaGetSymbolAddress((void**)&xh, g_x);
    cudaGetSymbolAddress((void**)&h1, g_h1);
    cudaGetSymbolAddress((void**)&h2, g_h2);
    cudaGetSymbolAddress((void**)&w1, g_w1);
    cudaGetSymbolAddress((void**)&w2, g_w2);
    cudaGetSymbolAddress((void**)&w3, g_w3);
    cudaGetSymbolAddress((void**)&lg, g_logits);

    const int smem = NSTAGE * STAGE_BYTES;   // 96 KB -> 2 CTAs/SM (192 of 228 KB)
    cudaFuncSetAttribute(gemm_mma<1, 0>, cudaFuncAttributeMaxDynamicSharedMemorySize, smem);
    cudaFuncSetAttribute(gemm_mma<2, 0>, cudaFuncAttributeMaxDynamicSharedMemorySize, smem);
    cudaFuncSetAttribute(gemm_mma<0, 1>, cudaFuncAttributeMaxDynamicSharedMemorySize, smem);

    // input conversions (coalesced tiled transposes)
    tohalf_kernel<<<(BB * DD + 255) / 256, 256>>>(x, xh, (size_t)BB * DD);
    transpose_half_tiled<<<dim3(DD / 32, HH / 32), dim3(32, 8)>>>(W1, w1, DD, HH);
    transpose_half_tiled<<<dim3(HH / 32, HH / 32), dim3(32, 8)>>>(W2, w2, HH, HH);
    transpose_half_tiled<<<dim3(HH / 32, OPAD / 32), dim3(32, 8)>>>(W3, w3, HH, OO);

    // L1: h1 = elu(x @ W1 + b1)
    gemm_mma<1, 0><<<dim3(HH / BN, BB / BM), 256, smem>>>(xh, w1, b1, h1, nullptr, DD, HH);
    // L2: h2 = sigmoid(h1 @ W2 + b2)
    gemm_mma<2, 0><<<dim3(HH / BN, BB / BM), 256, smem>>>(h1, w2, b2, h2, nullptr, HH, HH);
    // L3: logits = h2 @ W3 + b3  (padded stride OPAD)
    gemm_mma<0, 1><<<dim3(OPAD / BN, BB / BM), 256, smem>>>(h2, w3, b3, nullptr, lg, HH, OO);
    // segmented gumbel softmax
    gumbel_kernel<<<(BB * 32 + 255) / 256, 256>>>(lg, u, out);
}

// round 17
// speedup vs baseline: 1.5425x; 1.5425x over previous
#include <cuda_runtime.h>
#include <cuda_fp16.h>
#include <cstdint>
#include <math.h>

#define BB 32768
#define DD 128
#define HH 1024
#define OO 929
#define OPAD 1024

// ---------------- scratch (__device__ globals; allocation-free rule) -------
__device__ __half g_x[(size_t)BB * DD];
__device__ __half g_h1[(size_t)BB * HH];
__device__ __half g_h2[(size_t)BB * HH];
__device__ __half g_w1[(size_t)HH * DD];    // [N][K]
__device__ __half g_w2[(size_t)HH * HH];    // [N][K]
__device__ __half g_w3[(size_t)OPAD * HH];  // [Npad][K]
__device__ __half g_logits[(size_t)BB * OPAD];   // fp16 logits (half the round-trip traffic)

// ---------------- portable PTX helpers (valid on target sm_103) -----------
__device__ __forceinline__ uint32_t smem_u32(const void* p) {
    uint32_t a;
    asm("{ .reg .u64 t; cvta.to.shared.u64 t, %1; cvt.u32.u64 %0, t; }" : "=r"(a) : "l"(p));
    return a;
}
__device__ __forceinline__ void cp16(uint32_t dst, const void* src) {
    asm volatile("cp.async.cg.shared.global [%0], [%1], 16;" :: "r"(dst), "l"(src) : "memory");
}
__device__ __forceinline__ void cp_commit() {
    asm volatile("cp.async.commit_group;" ::: "memory");
}
template <int N>
__device__ __forceinline__ void cp_wait() {
    asm volatile("cp.async.wait_group %0;" :: "n"(N) : "memory");
}
__device__ __forceinline__ void ldsm_x4(uint32_t* r, uint32_t addr) {
    asm volatile("ldmatrix.sync.aligned.m8n8.x4.shared.b16 {%0,%1,%2,%3}, [%4];"
                 : "=r"(r[0]), "=r"(r[1]), "=r"(r[2]), "=r"(r[3]) : "r"(addr));
}
__device__ __forceinline__ void mma_f16(float* c, const uint32_t* a, uint32_t b0, uint32_t b1) {
    asm volatile(
        "mma.sync.aligned.m16n8k16.row.col.f32.f16.f16.f32 "
        "{%0,%1,%2,%3}, {%4,%5,%6,%7}, {%8,%9}, {%0,%1,%2,%3};"
        : "+f"(c[0]), "+f"(c[1]), "+f"(c[2]), "+f"(c[3])
        : "r"(a[0]), "r"(a[1]), "r"(a[2]), "r"(a[3]), "r"(b0), "r"(b1));
}

// ---------------- conversion kernels ---------------------------------------
__global__ void tohalf_kernel(const float* __restrict__ in, __half* __restrict__ out, size_t n) {
    size_t i = (size_t)blockIdx.x * 256 + threadIdx.x;
    if (i >= n) return;
    out[i] = __float2half(in[i]);
}

// Coalesced 32x32 tiled transpose: out[n*K + k] = half(W[k*N + n]), zero-pad n>=N.
// grid = (K/32, Npad/32), block = (32, 8). K and Npad are multiples of 32.
__global__ void transpose_half_tiled(const float* __restrict__ W,
                                     __half* __restrict__ outw,
                                     int K, int N) {
    __shared__ float t[32][33];
    const int k0 = blockIdx.x * 32, n0 = blockIdx.y * 32;
    const int tx = threadIdx.x, ty = threadIdx.y;
#pragma unroll
    for (int i = 0; i < 4; i++) {
        int k = k0 + ty + i * 8;
        int n = n0 + tx;
        t[ty + i * 8][tx] = (n < N) ? W[(size_t)k * N + n] : 0.f;
    }
    __syncthreads();
#pragma unroll
    for (int i = 0; i < 4; i++) {
        int n = n0 + ty + i * 8;
        int k = k0 + tx;
        outw[(size_t)n * K + k] = __float2half(t[tx][ty + i * 8]);
    }
}

// ---------------- mma.sync fp16 GEMM ----------------------------------------
// C(128x128) = act(A[M,K] @ B^T[N,K] + bias), A and B plain fp16.
// 256 threads = 8 warps, warp tile 32x64. BK=64 (128B rows, xor-8 swizzle),
// 3-stage cp.async pipeline, 96 KB smem -> 2 CTAs/SM.
#define BM 128
#define BN 128
#define BK 64
#define NSTAGE 3
// stage: 2 arrays of [128 rows][128B] = 16KB each
#define OFF_A   0
#define OFF_B   16384
#define STAGE_BYTES 32768

__device__ __forceinline__ void load_stage(uint32_t sbase,
    const __half* A, const __half* B, int K, int k0, int tid)
{
#pragma unroll
    for (int t = 0; t < 4; t++) {
        int id = tid + t * 256;            // 0..1023 over 128 rows x 8 chunks
        int r = id >> 3;
        int c = id & 7;
        int sc = c ^ (r & 7);              // xor swizzle, 16B granules, 8-wide
        uint32_t doff = (uint32_t)(r * 128 + sc * 16);
        size_t goff = (size_t)r * K + k0 + c * 8;
        cp16(sbase + OFF_A + doff, A + goff);
        cp16(sbase + OFF_B + doff, B + goff);
    }
}

// ACT: 0=none 1=elu 2=sigmoid.
// EPI: 0=write fp16 activations (stride HH), 1=write fp16 logits (stride OPAD, guard col<Ncols)
template <int ACT, int EPI>
__global__ __launch_bounds__(256, 2)
void gemm_mma(const __half* __restrict__ A0, const __half* __restrict__ B0,
              const float* __restrict__ bias,
              __half* __restrict__ Ch, __half* __restrict__ Cf, int K, int Ncols)
{
    extern __shared__ char smem[];
    const uint32_t sm0 = smem_u32(smem);
    const int tid = threadIdx.x;
    const int wid = tid >> 5;
    const int lane = tid & 31;
    const int wm = wid & 3;                // 4 m-slices of 32
    const int wn = wid >> 2;               // 2 n-slices of 64
    const int bm = blockIdx.y * BM;
    const int bn = blockIdx.x * BN;

    const __half* A = A0 + (size_t)bm * K;
    const __half* B = B0 + (size_t)bn * K;

    const int KT = K / BK;

    float acc[2][8][4];
#pragma unroll
    for (int i = 0; i < 2; i++)
#pragma unroll
        for (int j = 0; j < 8; j++)
#pragma unroll
            for (int q = 0; q < 4; q++) acc[i][j][q] = 0.f;

    // ldmatrix per-lane address components
    const int a_moff = lane & 15;
    const int a_kadd = lane >> 4;                       // 0/1
    const int b_noff = (lane & 7) | ((lane & 16) >> 1); // 0..15
    const int b_kadd = (lane >> 3) & 1;

    // prologue: fill NSTAGE-1 stages
#pragma unroll
    for (int s = 0; s < NSTAGE - 1; s++) {
        if (s < KT) load_stage(sm0 + s * STAGE_BYTES, A, B, K, s * BK, tid);
        cp_commit();
    }

    for (int kt = 0; kt < KT; kt++) {
        cp_wait<NSTAGE - 2>();
        __syncthreads();
        // Single barrier: it also proves every warp finished reading stage
        // (kt-1)%NSTAGE, which is the one the next load overwrites.

        int nk = kt + NSTAGE - 1;
        if (nk < KT)
            load_stage(sm0 + (nk % NSTAGE) * STAGE_BYTES, A, B, K, nk * BK, tid);
        cp_commit();

        const uint32_t sbase = sm0 + (kt % NSTAGE) * STAGE_BYTES;

#pragma unroll
        for (int s = 0; s < 4; s++) {                 // four k16 steps in BK=64
            uint32_t af[2][4];
            const int kca = 2 * s + a_kadd;           // 0..7 granules
#pragma unroll
            for (int i = 0; i < 2; i++) {
                int r = wm * 32 + i * 16 + a_moff;
                uint32_t off = (uint32_t)(r * 128 + ((kca ^ (r & 7)) * 16));
                ldsm_x4(af[i], sbase + OFF_A + off);
            }
            const int kcb = 2 * s + b_kadd;
#pragma unroll
            for (int jp = 0; jp < 4; jp++) {
                uint32_t bf[4];
                int rn = wn * 64 + jp * 16 + b_noff;
                uint32_t off = (uint32_t)(rn * 128 + ((kcb ^ (rn & 7)) * 16));
                ldsm_x4(bf, sbase + OFF_B + off);
#pragma unroll
                for (int i = 0; i < 2; i++) {
                    mma_f16(acc[i][2 * jp],     af[i], bf[0], bf[1]);
                    mma_f16(acc[i][2 * jp + 1], af[i], bf[2], bf[3]);
                }
            }
        }
    }

    // ---- epilogue ----
#pragma unroll
    for (int i = 0; i < 2; i++) {
#pragma unroll
        for (int j = 0; j < 8; j++) {
            const int row0 = bm + wm * 32 + i * 16 + (lane >> 2);
            const int col = bn + wn * 64 + j * 8 + (lane & 3) * 2;
            if (EPI == 0) {
                float bi0 = bias[col], bi1 = bias[col + 1];
#pragma unroll
                for (int h = 0; h < 2; h++) {       // h=0: rows l/4, h=1: +8
                    int row = row0 + h * 8;
                    float v0 = acc[i][j][2 * h] + bi0;
                    float v1 = acc[i][j][2 * h + 1] + bi1;
                    if (ACT == 1) {
                        v0 = (v0 > 0.f) ? v0 : expm1f(v0);
                        v1 = (v1 > 0.f) ? v1 : expm1f(v1);
                    } else if (ACT == 2) {
                        v0 = 1.f / (1.f + __expf(-v0));
                        v1 = 1.f / (1.f + __expf(-v1));
                    }
                    __half2 h2;
                    h2.x = __float2half(v0);
                    h2.y = __float2half(v1);
                    *(__half2*)(Ch + (size_t)row * HH + col) = h2;
                }
            } else {
#pragma unroll
                for (int h = 0; h < 2; h++) {
                    int row = row0 + h * 8;
                    if (col + 1 < Ncols) {
                        __half2 h2;
                        h2.x = __float2half(acc[i][j][2 * h] + bias[col]);
                        h2.y = __float2half(acc[i][j][2 * h + 1] + bias[col + 1]);
                        *(__half2*)(Cf + (size_t)row * OPAD + col) = h2;
                    } else if (col < Ncols) {
                        Cf[(size_t)row * OPAD + col] = __float2half(acc[i][j][2 * h] + bias[col]);
                    }
                }
            }
        }
    }
}

// ---------------- Gumbel-softmax (fp16 logits, no-max formulation) ---------
// Safe without max subtraction: y = (logit + g)/0.8 with g in [-3.8, ~16.5]
// and |logit| small -> y <= ~21, exp(y) <= 1.3e9, segment sums < 1e12 << FLT_MAX.
// All segments keep e values in registers (measured fastest in R11/R12 probes).
__device__ __forceinline__ float warp_sum(float v) {
#pragma unroll
    for (int d = 16; d; d >>= 1) v += __shfl_xor_sync(0xffffffffu, v, d);
    return v;
}

__device__ __forceinline__ float gumbel_e(float logit, float uu) {
    float g = -__logf(-__logf(uu + 1e-20f) + 1e-20f);
    return __expf((logit + g) * 1.25f);
}

template <int N>
__device__ __forceinline__ void seg_softmax(const __half* __restrict__ lrow,
                                            const float* __restrict__ urow,
                                            float* __restrict__ orow,
                                            int off, int lane)
{
    constexpr int NI = (N + 31) / 32;
    float y[NI];
    float s = 0.f;
#pragma unroll
    for (int i = 0; i < NI; i++) {
        int idx = lane + i * 32;
        float e = 0.f;
        if (idx < N) e = gumbel_e(__half2float(lrow[off + idx]), urow[off + idx]);
        y[i] = e;
        s += e;
    }
    s = warp_sum(s);
    float inv = 1.f / s;
#pragma unroll
    for (int i = 0; i < NI; i++) {
        int idx = lane + i * 32;
        if (idx < N) orow[off + idx] = y[i] * inv;
    }
}

__global__ __launch_bounds__(256)
void gumbel_kernel(const __half* __restrict__ logits,
                   const float* __restrict__ u,
                   float* __restrict__ out)
{
    int w = (blockIdx.x * 256 + threadIdx.x) >> 5;
    int lane = threadIdx.x & 31;
    if (w >= BB) return;
    const __half* lrow = logits + (size_t)w * OPAD;
    const float* urow = u + (size_t)w * OO;
    float* orow = out + (size_t)w * OO;

    seg_softmax<29>(lrow, urow, orow, 0, lane);
    seg_softmax<2>(lrow, urow, orow, 29, lane);
    if (lane == 0) orow[31] = __half2float(lrow[31]);
    seg_softmax<6>(lrow, urow, orow, 32, lane);
    seg_softmax<7>(lrow, urow, orow, 38, lane);
    seg_softmax<59>(lrow, urow, orow, 45, lane);
    if (lane == 0) orow[104] = __half2float(lrow[104]);
    seg_softmax<24>(lrow, urow, orow, 105, lane);
    seg_softmax<76>(lrow, urow, orow, 129, lane);
    seg_softmax<711>(lrow, urow, orow, 205, lane);
    seg_softmax<3>(lrow, urow, orow, 916, lane);
    seg_softmax<9>(lrow, urow, orow, 919, lane);
    if (lane == 0) orow[928] = __half2float(lrow[928]);
}

// ---------------------------------------------------------------------------
extern "C" void kernel_launch(void* const* d_in, const int* in_sizes, int n_in,
                              void* d_out, int out_size)
{
    const float* x  = (const float*)d_in[0];
    const float* W1 = (const float*)d_in[1];
    const float* b1 = (const float*)d_in[2];
    const float* W2 = (const float*)d_in[3];
    const float* b2 = (const float*)d_in[4];
    const float* W3 = (const float*)d_in[5];
    const float* b3 = (const float*)d_in[6];
    const float* u  = (const float*)d_in[7];
    float* out = (float*)d_out;

    __half *xh, *h1, *h2, *w1, *w2, *w3, *lg;
    cudaGetSymbolAddress((void**)&xh, g_x);
    cudaGetSymbolAddress((void**)&h1, g_h1);
    cudaGetSymbolAddress((void**)&h2, g_h2);
    cudaGetSymbolAddress((void**)&w1, g_w1);
    cudaGetSymbolAddress((void**)&w2, g_w2);
    cudaGetSymbolAddress((void**)&w3, g_w3);
    cudaGetSymbolAddress((void**)&lg, g_logits);

    const int smem = NSTAGE * STAGE_BYTES;   // 96 KB -> 2 CTAs/SM (192 of 228 KB)
    cudaFuncSetAttribute(gemm_mma<1, 0>, cudaFuncAttributeMaxDynamicSharedMemorySize, smem);
    cudaFuncSetAttribute(gemm_mma<2, 0>, cudaFuncAttributeMaxDynamicSharedMemorySize, smem);
    cudaFuncSetAttribute(gemm_mma<0, 1>, cudaFuncAttributeMaxDynamicSharedMemorySize, smem);

    // input conversions (coalesced tiled transposes)
    tohalf_kernel<<<(BB * DD + 255) / 256, 256>>>(x, xh, (size_t)BB * DD);
    transpose_half_tiled<<<dim3(DD / 32, HH / 32), dim3(32, 8)>>>(W1, w1, DD, HH);
    transpose_half_tiled<<<dim3(HH / 32, HH / 32), dim3(32, 8)>>>(W2, w2, HH, HH);
    transpose_half_tiled<<<dim3(HH / 32, OPAD / 32), dim3(32, 8)>>>(W3, w3, HH, OO);

    // L1: h1 = elu(x @ W1 + b1)
    gemm_mma<1, 0><<<dim3(HH / BN, BB / BM), 256, smem>>>(xh, w1, b1, h1, nullptr, DD, HH);
    // L2: h2 = sigmoid(h1 @ W2 + b2)
    gemm_mma<2, 0><<<dim3(HH / BN, BB / BM), 256, smem>>>(h1, w2, b2, h2, nullptr, HH, HH);
    // L3: logits = h2 @ W3 + b3  (fp16, padded stride OPAD)
    gemm_mma<0, 1><<<dim3(OPAD / BN, BB / BM), 256, smem>>>(h2, w3, b3, nullptr, lg, HH, OO);
    // segmented gumbel softmax
    gumbel_kernel<<<(BB * 32 + 255) / 256, 256>>>(lg, u, out);
}